// round 1
// baseline (speedup 1.0000x reference)
#include <cuda_runtime.h>
#include <cstdint>

// ---------------------------------------------------------------------------
// RolloutModule: B=32768 closed-loop rollouts of a 13->256->256->256->2 MLP
// policy for 64 steps, with STREL robustness reduction.
//
// Layout: 1024 CTAs x 256 threads. CTA owns 32 batch lanes for the whole
// rollout. Activations in SMEM as duplicated float2 so fma.rn.f32x2 (packed
// dual fp32 FMA, Blackwell) can consume them with one LDS.64 broadcast.
// W2/W3 streamed L2->SMEM with cp.async double buffering (32-row tiles).
// STREL accumulators kept as online max-shifted logsumexp in registers of
// threads 0..31.
// ---------------------------------------------------------------------------

#define THREADS 256
#define TILE_B  32
#define ROWF2   257   // float2 row stride for activation arrays (pad 1 to break bank alignment)

typedef unsigned long long ull;

__device__ __forceinline__ ull pack2(float lo, float hi) {
    ull r; asm("mov.b64 %0, {%1,%2};" : "=l"(r) : "f"(lo), "f"(hi)); return r;
}
__device__ __forceinline__ void unpack2(ull v, float& lo, float& hi) {
    asm("mov.b64 {%0,%1}, %2;" : "=f"(lo), "=f"(hi) : "l"(v));
}
__device__ __forceinline__ void fma2(ull& acc, ull a, ull b) {
    asm("fma.rn.f32x2 %0, %1, %2, %0;" : "+l"(acc) : "l"(a), "l"(b));
}
__device__ __forceinline__ void cp16(uint32_t dst, const void* src) {
    asm volatile("cp.async.cg.shared.global [%0], [%1], 16;" :: "r"(dst), "l"(src));
}
__device__ __forceinline__ void cp_commit() { asm volatile("cp.async.commit_group;"); }
template<int N> __device__ __forceinline__ void cp_wait() {
    asm volatile("cp.async.wait_group %0;" :: "n"(N));
}

// SMEM float offsets
// Wbuf   [2][8192]           : 0      .. 16384
// W1s    [13*256]            : 16384  .. 19712
// actA   32 rows * 257 f2    : 19712  .. 36160   (floats)
// actB   same                : 36160  .. 52608
// b1S/b2S/b3S [256] each     : 52608 / 52864 / 53120
// wmuS   [512]               : 53376
// bmuS   [2] (+2 pad)        : 53888
// obsS   32*13 float2        : 53892  .. 54724
// aS     [64]                : 54724  .. 54788
#define SMEM_FLOATS 54788
#define SMEM_BYTES  (SMEM_FLOATS * 4)

__device__ __forceinline__ void write_obs(float2* obsS, int b, float px, float py) {
    float2* o = obsS + b * 13;
    const float iw = 0.1f;  // 1/WS
    float v;
    v = px * iw;          o[0] = make_float2(v, v);
    v = py * iw;          o[1] = make_float2(v, v);
    v = (4.0f - px) * iw; o[2] = make_float2(v, v);
    v = (3.0f - py) * iw; o[3] = make_float2(v, v);
    const float ox[3]  = {1.75f, 1.75f, 3.75f};
    const float oy[3]  = {1.75f, 3.75f, 2.00f};
    const float orr[3] = {0.38f, 0.42f, 0.34f};
    #pragma unroll
    for (int i = 0; i < 3; i++) {
        float dx = px - ox[i], dy = py - oy[i];
        float dist = sqrtf(dx * dx + dy * dy + 1e-9f);
        v = -dx * iw;      o[4 + 2 * i] = make_float2(v, v);
        v = -dy * iw;      o[5 + 2 * i] = make_float2(v, v);
        v = dist - orr[i]; o[10 + i]    = make_float2(v, v);
    }
}

// One 256->256 layer: out = relu(in @ W + bias). W streamed from global
// (L2-resident) in 8 tiles of 32 rows, double buffered via cp.async.
__device__ __forceinline__ void layer256(
    const float2* __restrict__ inAct, float2* __restrict__ outAct,
    const float* __restrict__ Wg, const float* __restrict__ biasS,
    float* Wbuf, int tx)
{
    const int jq = tx & 63;   // output quad: j = jq*4 .. jq*4+3
    const int bg = tx >> 6;   // batch octet: b = bg*8 .. bg*8+7

    ull acc[8][2];
    {
        float4 bj = *(const float4*)&biasS[jq * 4];
        ull p01 = pack2(bj.x, bj.y), p23 = pack2(bj.z, bj.w);
        #pragma unroll
        for (int i = 0; i < 8; i++) { acc[i][0] = p01; acc[i][1] = p23; }
    }

    uint32_t wb0 = (uint32_t)__cvta_generic_to_shared(Wbuf);
    // prefetch tile 0 into buffer 0
    {
        const float4* src = (const float4*)Wg;
        #pragma unroll
        for (int r = 0; r < 8; r++) cp16(wb0 + (tx + r * 256) * 16, src + tx + r * 256);
        cp_commit();
    }

    const ull* inBase = (const ull*)(inAct + bg * 8 * ROWF2);

    #pragma unroll 1
    for (int kt = 0; kt < 8; kt++) {
        if (kt < 7) {
            uint32_t dst = wb0 + ((kt + 1) & 1) * 32768u;
            const float4* src = (const float4*)(Wg + (kt + 1) * 8192);
            #pragma unroll
            for (int r = 0; r < 8; r++) cp16(dst + (tx + r * 256) * 16, src + tx + r * 256);
            cp_commit();
            cp_wait<1>();
        } else {
            cp_wait<0>();
        }
        __syncthreads();

        const float* cur = Wbuf + (kt & 1) * 8192;
        const int kbase = kt * 32;
        #pragma unroll 4
        for (int kk = 0; kk < 32; kk++) {
            float4 w4 = *(const float4*)&cur[kk * 256 + jq * 4];
            ull w01 = pack2(w4.x, w4.y), w23 = pack2(w4.z, w4.w);
            #pragma unroll
            for (int i = 0; i < 8; i++) {
                ull a = inBase[i * ROWF2 + kbase + kk];  // LDS.64 broadcast of dup act
                fma2(acc[i][0], a, w01);
                fma2(acc[i][1], a, w23);
            }
        }
        __syncthreads();
    }

    // epilogue: relu + duplicated store
    #pragma unroll
    for (int i = 0; i < 8; i++) {
        float v0, v1, v2, v3;
        unpack2(acc[i][0], v0, v1);
        unpack2(acc[i][1], v2, v3);
        v0 = fmaxf(v0, 0.f); v1 = fmaxf(v1, 0.f);
        v2 = fmaxf(v2, 0.f); v3 = fmaxf(v3, 0.f);
        float2* orow = outAct + (bg * 8 + i) * ROWF2 + jq * 4;
        orow[0] = make_float2(v0, v0);
        orow[1] = make_float2(v1, v1);
        orow[2] = make_float2(v2, v2);
        orow[3] = make_float2(v3, v3);
    }
}

__global__ void __launch_bounds__(THREADS, 1)
rollout_kernel(const float* __restrict__ pos0, const float* __restrict__ wind,
               const float* __restrict__ w1,  const float* __restrict__ b1g,
               const float* __restrict__ w2,  const float* __restrict__ b2g,
               const float* __restrict__ w3,  const float* __restrict__ b3g,
               const float* __restrict__ wmu, const float* __restrict__ bmug,
               float* __restrict__ out)
{
    extern __shared__ float sm[];
    float*  Wbuf = sm;                        // [2][8192]
    float*  W1s  = sm + 16384;                // [13*256]
    float2* actA = (float2*)(sm + 19712);
    float2* actB = (float2*)(sm + 36160);
    float*  b1S  = sm + 52608;
    float*  b2S  = sm + 52864;
    float*  b3S  = sm + 53120;
    float*  wmuS = sm + 53376;                // [512]
    float*  bmuS = sm + 53888;                // [2]
    float2* obsS = (float2*)(sm + 53892);     // 32 x 13
    float*  aS   = sm + 54724;                // [64]

    const int tx = threadIdx.x;
    const int b0 = blockIdx.x * TILE_B;

    // stage persistent weights / biases
    for (int i = tx; i < 832; i += THREADS) ((float4*)W1s)[i] = ((const float4*)w1)[i];
    for (int i = tx; i < 256; i += THREADS) { b1S[i] = b1g[i]; b2S[i] = b2g[i]; b3S[i] = b3g[i]; }
    for (int i = tx; i < 512; i += THREADS) wmuS[i] = wmu[i];
    if (tx < 2) bmuS[tx] = bmug[tx];

    // per-lane rollout state (threads 0..31 own one batch element each)
    float px = 0.f, py = 0.f, wx = 0.f, wy = 0.f;
    float m_s = -1e30f, s_s = 0.f, m_r = -1e30f, s_r = 0.f;
    if (tx < TILE_B) {
        px = pos0[(b0 + tx) * 2 + 0]; py = pos0[(b0 + tx) * 2 + 1];
        wx = wind[(b0 + tx) * 2 + 0]; wy = wind[(b0 + tx) * 2 + 1];
        write_obs(obsS, tx, px, py);
    }
    __syncthreads();

    #pragma unroll 1
    for (int t = 0; t < 64; t++) {
        // ---- layer 1: obs(13) -> actA (W1 resident in SMEM) ----
        {
            const int jq = tx & 63, bg = tx >> 6;
            ull acc[8][2];
            float4 bj = *(const float4*)&b1S[jq * 4];
            ull p01 = pack2(bj.x, bj.y), p23 = pack2(bj.z, bj.w);
            #pragma unroll
            for (int i = 0; i < 8; i++) { acc[i][0] = p01; acc[i][1] = p23; }
            const ull* ob = (const ull*)obsS;
            #pragma unroll
            for (int k = 0; k < 13; k++) {
                float4 w4 = *(const float4*)&W1s[k * 256 + jq * 4];
                ull w01 = pack2(w4.x, w4.y), w23 = pack2(w4.z, w4.w);
                #pragma unroll
                for (int i = 0; i < 8; i++) {
                    ull a = ob[(bg * 8 + i) * 13 + k];
                    fma2(acc[i][0], a, w01);
                    fma2(acc[i][1], a, w23);
                }
            }
            #pragma unroll
            for (int i = 0; i < 8; i++) {
                float v0, v1, v2, v3;
                unpack2(acc[i][0], v0, v1);
                unpack2(acc[i][1], v2, v3);
                v0 = fmaxf(v0, 0.f); v1 = fmaxf(v1, 0.f);
                v2 = fmaxf(v2, 0.f); v3 = fmaxf(v3, 0.f);
                float2* orow = actA + (bg * 8 + i) * ROWF2 + jq * 4;
                orow[0] = make_float2(v0, v0);
                orow[1] = make_float2(v1, v1);
                orow[2] = make_float2(v2, v2);
                orow[3] = make_float2(v3, v3);
            }
        }

        // ---- layers 2 & 3 ----
        layer256(actA, actB, w2, b2S, Wbuf, tx);
        layer256(actB, actA, w3, b3S, Wbuf, tx);
        __syncthreads();

        // ---- output head: a = clip(h3 @ wmu + bmu) ----
        if (tx < 64) {
            int j = tx >> 5, b = tx & 31;
            const float* row = (const float*)(actA + b * ROWF2);  // read .x of dup float2
            float a0 = bmuS[j], a1 = 0.f, a2 = 0.f, a3 = 0.f;
            #pragma unroll 8
            for (int k = 0; k < 256; k += 4) {
                a0 = fmaf(row[2 * k],     wmuS[2 * k + j],     a0);
                a1 = fmaf(row[2 * k + 2], wmuS[2 * k + 2 + j], a1);
                a2 = fmaf(row[2 * k + 4], wmuS[2 * k + 4 + j], a2);
                a3 = fmaf(row[2 * k + 6], wmuS[2 * k + 6 + j], a3);
            }
            float acc = (a0 + a1) + (a2 + a3);
            aS[b * 2 + j] = fminf(fmaxf(acc, -1.f), 1.f);
        }
        __syncthreads();

        // ---- dynamics + STREL accumulators + next obs ----
        if (tx < TILE_B) {
            float vx = 2.f * aS[tx * 2 + 0] + wx;
            float vy = 2.f * aS[tx * 2 + 1] + wy;
            #pragma unroll
            for (int s = 0; s < 4; s++) {
                px = fminf(fmaxf(px + 0.0625f * vx, -4.f), 10.f);
                py = fminf(fmaxf(py + 0.0625f * vy, -4.f), 10.f);
            }
            // spatial smooth-min clearance (beta=50), max-shifted
            float dx = px - 1.75f, dy = py - 1.75f;
            float x0 = -50.f * (sqrtf(dx * dx + dy * dy + 1e-9f) - 0.38f);
            dx = px - 1.75f; dy = py - 3.75f;
            float x1 = -50.f * (sqrtf(dx * dx + dy * dy + 1e-9f) - 0.42f);
            dx = px - 3.75f; dy = py - 2.00f;
            float x2 = -50.f * (sqrtf(dx * dx + dy * dy + 1e-9f) - 0.34f);
            float mm = fmaxf(x0, fmaxf(x1, x2));
            float safe = -(mm + logf(expf(x0 - mm) + expf(x1 - mm) + expf(x2 - mm))) * 0.02f;

            float dgx = px - 4.f, dgy = py - 3.f;
            float reach = 0.45f - sqrtf(dgx * dgx + dgy * dgy + 1e-9f);

            // online max-shifted logsumexp accumulators (beta=8)
            float xs = -8.f * safe;
            if (xs > m_s) { s_s = s_s * expf(m_s - xs) + 1.f; m_s = xs; }
            else          { s_s += expf(xs - m_s); }
            float xr = 8.f * reach;
            if (xr > m_r) { s_r = s_r * expf(m_r - xr) + 1.f; m_r = xr; }
            else          { s_r += expf(xr - m_r); }

            write_obs(obsS, tx, px, py);
        }
        __syncthreads();
    }

    if (tx < TILE_B) {
        float rho_safe  = -(m_s + logf(s_s)) * 0.125f;
        float rho_reach =  (m_r + logf(s_r)) * 0.125f;
        float u0 = -8.f * rho_safe, u1 = -8.f * rho_reach;
        float mm = fmaxf(u0, u1);
        float rho = -(mm + logf(expf(u0 - mm) + expf(u1 - mm))) * 0.125f;
        out[b0 + tx] = rho;
    }
}

extern "C" void kernel_launch(void* const* d_in, const int* in_sizes, int n_in,
                              void* d_out, int out_size) {
    const float* pos0 = (const float*)d_in[0];
    const float* wind = (const float*)d_in[1];
    const float* w1   = (const float*)d_in[2];
    const float* b1   = (const float*)d_in[3];
    const float* w2   = (const float*)d_in[4];
    const float* b2   = (const float*)d_in[5];
    const float* w3   = (const float*)d_in[6];
    const float* b3   = (const float*)d_in[7];
    const float* wmu  = (const float*)d_in[8];
    const float* bmu  = (const float*)d_in[9];
    float* out = (float*)d_out;

    cudaFuncSetAttribute(rollout_kernel,
                         cudaFuncAttributeMaxDynamicSharedMemorySize, SMEM_BYTES);

    int grid = out_size / TILE_B;  // 32768/32 = 1024
    rollout_kernel<<<grid, THREADS, SMEM_BYTES>>>(pos0, wind, w1, b1, w2, b2,
                                                  w3, b3, wmu, bmu, out);
}